// round 2
// baseline (speedup 1.0000x reference)
#include <cuda_runtime.h>
#include <cuda_bf16.h>
#include <cstdint>

// Problem constants (from reference)
#define BSZ 512
#define DIM 128
#define NCLS 64
#define MARGIN 0.2f

// Scratch (no allocations allowed in kernel_launch)
__device__ float g_dist[BSZ * BSZ];   // 1 MB distance matrix
__device__ float g_psum[BSZ];         // per-anchor-row partial sums
__device__ int   g_pcnt[BSZ];         // per-anchor-row valid-pair counts

// ---------------------------------------------------------------------------
// Kernel A: pairwise Euclidean distance matrix, diff-based (matches reference
// sq = sum((a-b)^2) formulation; dist = sq>0 ? sqrt(sq) : 0).
// TILE=32, block (16,16), each thread computes a 2x2 micro-tile.
// ---------------------------------------------------------------------------
__global__ __launch_bounds__(256, 4)
void dist_kernel(const float* __restrict__ emb) {
    __shared__ float sA[32][65];   // pad 65: conflict-free (broadcast) reads
    __shared__ float sB[32][65];

    const int tx = threadIdx.x, ty = threadIdx.y;
    const int tid = ty * 16 + tx;
    const int i0 = blockIdx.y * 32;
    const int j0 = blockIdx.x * 32;

    float acc00 = 0.f, acc01 = 0.f, acc10 = 0.f, acc11 = 0.f;

    #pragma unroll
    for (int kb = 0; kb < 2; kb++) {           // two 64-dim chunks of D=128
        // Load 32x64 chunks of A-rows and B-rows: 512 float4 each, 2/thread
        #pragma unroll
        for (int t = tid; t < 512; t += 256) {
            int row = t >> 4;        // 0..31
            int c4  = t & 15;        // 0..15 -> float4 within 64-col chunk
            const float4 va = *(const float4*)(emb + (size_t)(i0 + row) * DIM + kb * 64 + c4 * 4);
            sA[row][c4 * 4 + 0] = va.x;
            sA[row][c4 * 4 + 1] = va.y;
            sA[row][c4 * 4 + 2] = va.z;
            sA[row][c4 * 4 + 3] = va.w;
            const float4 vb = *(const float4*)(emb + (size_t)(j0 + row) * DIM + kb * 64 + c4 * 4);
            sB[row][c4 * 4 + 0] = vb.x;
            sB[row][c4 * 4 + 1] = vb.y;
            sB[row][c4 * 4 + 2] = vb.z;
            sB[row][c4 * 4 + 3] = vb.w;
        }
        __syncthreads();

        #pragma unroll 8
        for (int d = 0; d < 64; d++) {
            const float a0 = sA[ty * 2 + 0][d];
            const float a1 = sA[ty * 2 + 1][d];
            const float b0 = sB[tx * 2 + 0][d];
            const float b1 = sB[tx * 2 + 1][d];
            float t00 = a0 - b0; acc00 = fmaf(t00, t00, acc00);
            float t01 = a0 - b1; acc01 = fmaf(t01, t01, acc01);
            float t10 = a1 - b0; acc10 = fmaf(t10, t10, acc10);
            float t11 = a1 - b1; acc11 = fmaf(t11, t11, acc11);
        }
        __syncthreads();
    }

    const int i = i0 + ty * 2;
    const int j = j0 + tx * 2;
    g_dist[(size_t)(i + 0) * BSZ + (j + 0)] = acc00 > 0.f ? sqrtf(acc00) : 0.f;
    g_dist[(size_t)(i + 0) * BSZ + (j + 1)] = acc01 > 0.f ? sqrtf(acc01) : 0.f;
    g_dist[(size_t)(i + 1) * BSZ + (j + 0)] = acc10 > 0.f ? sqrtf(acc10) : 0.f;
    g_dist[(size_t)(i + 1) * BSZ + (j + 1)] = acc11 > 0.f ? sqrtf(acc11) : 0.f;
}

// ---------------------------------------------------------------------------
// Kernel B: mining. One block (512 threads) per anchor row i.
// For each positive p (p>i, same label):
//   j_min = first j with neg[j] && d_ap < d[j] < d_ap+margin
//   found  -> d_an = drow[rank[j_min]]   (rank = #negatives before j_min;
//                                         this replicates the reference quirk)
//   !found -> d_an = drow[j0]            (j0 = first negative index, 0 if none)
//   per_pair = relu(d_ap^2 - d_an^2 + margin)
// Deterministic: per-p results land in pp[p], reduced in fixed tree order.
// ---------------------------------------------------------------------------
__global__ __launch_bounds__(BSZ, 2)
void mine_kernel(const int* __restrict__ labels) {
    const int i   = blockIdx.x;
    const int tid = threadIdx.x;

    __shared__ float drow[BSZ];
    __shared__ int   slab[BSZ];
    __shared__ int   rk[BSZ];
    __shared__ float pp[BSZ];
    __shared__ int   sj0;

    drow[tid] = g_dist[(size_t)i * BSZ + tid];
    slab[tid] = labels[tid];
    if (tid == 0) sj0 = 0x7fffffff;
    __syncthreads();

    const int li  = slab[i];
    const int neg = (slab[tid] != li) ? 1 : 0;
    if (neg) atomicMin(&sj0, tid);
    rk[tid] = neg;
    __syncthreads();

    // Hillis-Steele inclusive scan of neg flags
    #pragma unroll
    for (int off = 1; off < BSZ; off <<= 1) {
        int v = (tid >= off) ? rk[tid - off] : 0;
        __syncthreads();
        rk[tid] += v;
        __syncthreads();
    }
    const int myrank = rk[tid] - neg;   // exclusive prefix = rank
    __syncthreads();
    rk[tid] = myrank;
    pp[tid] = 0.f;
    __syncthreads();

    const int j0   = (sj0 == 0x7fffffff) ? 0 : sj0;  // argmax(all-false)=0
    const int warp = tid >> 5;
    const int lane = tid & 31;

    // 16 warps stride over candidate positives p in (i, 512)
    for (int p = i + 1 + warp; p < BSZ; p += 16) {
        if (slab[p] != li) continue;            // warp-uniform
        const float dap = drow[p];
        const float hi  = dap + MARGIN;
        int minj = BSZ;
        for (int j = lane; j < BSZ; j += 32) {  // increasing j per lane
            const float dj = drow[j];
            if (slab[j] != li && dj > dap && dj < hi) { minj = j; break; }
        }
        minj = __reduce_min_sync(0xffffffffu, minj);
        float dan;
        if (minj < BSZ) dan = drow[rk[minj]];   // reference quirk: index by rank
        else            dan = drow[j0];
        if (lane == 0) {
            const float v = fmaf(dap, dap, MARGIN) - dan * dan;
            pp[p] = v > 0.f ? v : 0.f;
        }
    }

    const int isPos = (tid > i && slab[tid] == li) ? 1 : 0;
    const int cnt = __syncthreads_count(isPos);  // barrier + deterministic count

    // Fixed-order tree reduction of pp
    #pragma unroll
    for (int s = 256; s > 0; s >>= 1) {
        if (tid < s) pp[tid] += pp[tid + s];
        __syncthreads();
    }
    if (tid == 0) {
        g_psum[i] = pp[0];
        g_pcnt[i] = cnt;
    }
}

// ---------------------------------------------------------------------------
// Kernel C: deterministic final reduction over the 512 row partials.
// ---------------------------------------------------------------------------
__global__ __launch_bounds__(BSZ, 1)
void finalize_kernel(float* __restrict__ out) {
    __shared__ float s[BSZ];
    __shared__ int   c[BSZ];
    const int tid = threadIdx.x;
    s[tid] = g_psum[tid];
    c[tid] = g_pcnt[tid];
    __syncthreads();
    #pragma unroll
    for (int st = 256; st > 0; st >>= 1) {
        if (tid < st) { s[tid] += s[tid + st]; c[tid] += c[tid + st]; }
        __syncthreads();
    }
    if (tid == 0) out[0] = s[0] / (float)c[0];
}

// ---------------------------------------------------------------------------
extern "C" void kernel_launch(void* const* d_in, const int* in_sizes, int n_in,
                              void* d_out, int out_size) {
    const float* emb    = (const float*)d_in[0];
    const int*   labels = (const int*)d_in[1];
    float*       out    = (float*)d_out;

    dim3 gA(16, 16), bA(16, 16);
    dist_kernel<<<gA, bA>>>(emb);
    mine_kernel<<<BSZ, BSZ>>>(labels);
    finalize_kernel<<<1, BSZ>>>(out);
}